// round 4
// baseline (speedup 1.0000x reference)
#include <cuda_runtime.h>

// PatchExtractor: crop(center square of bbox) + bilinear resize 224x224 + CLIP
// normalization. R3: shared-memory row staging with float4 coalesced loads.
//
// img    : [3, 2048, 2048] fp32
// bboxes : [N, 4] int32 (xyxy)
// out    : [N, 3, 224, 224] fp32

#define SIZE 224
#define IMG_W 2048
#define IMG_H 2048
#define PLANE (IMG_H * IMG_W)
#define OUT_PLANE (SIZE * SIZE)
#define MAX_N 1024

// smem tile: 6 row segments (2 src rows x 3 channels) x 328 floats, padded.
// STRIDE multiple of 4 keeps float4 stores aligned.
#define SEG_F4 82                  // float4 per segment (328 floats)
#define STRIDE 332                 // floats per segment row (pad vs 328)

#define MEAN_R 0.48145466f
#define MEAN_G 0.4578275f
#define MEAN_B 0.40821073f
#define STD_R  0.26862954f
#define STD_G  0.26130258f
#define STD_B  0.27577711f

// Per-patch geometry: {ax, ay, step, unused};  sx = ax + x*step
__device__ float4 g_geom[MAX_N];

__global__ void geom_kernel(const int* __restrict__ bboxes, int N)
{
    int n = blockIdx.x * blockDim.x + threadIdx.x;
    if (n >= N) return;
    const float x0 = (float)bboxes[4 * n + 0];
    const float y0 = (float)bboxes[4 * n + 1];
    const float x1 = (float)bboxes[4 * n + 2];
    const float y1 = (float)bboxes[4 * n + 3];
    const float side = fminf(x1 - x0, y1 - y0);
    const float step = side * (1.0f / (float)SIZE);
    const float ax = 0.5f * (x0 + x1) - 0.5f * side + 0.5f * step - 0.5f;
    const float ay = 0.5f * (y0 + y1) - 0.5f * side + 0.5f * step - 0.5f;
    g_geom[n] = make_float4(ax, ay, step, 0.0f);
}

__global__ __launch_bounds__(SIZE)
void patch_extract_kernel(const float* __restrict__ img,
                          float* __restrict__ out)
{
    __shared__ float tile[6 * STRIDE];

    const int y   = blockIdx.x;   // output row
    const int n   = blockIdx.y;   // patch
    const int tid = threadIdx.x;  // output col

    const float4 g = g_geom[n];

    // --- uniform per-block geometry (computed redundantly; cheap) ---
    float sy = fmaf((float)y, g.z, g.y);
    sy = fminf(fmaxf(sy, 0.0f), (float)(IMG_H - 1));
    const int   iy0 = (int)sy;
    const float fy  = sy - (float)iy0;

    float sx_first = fminf(fmaxf(g.x, 0.0f), (float)(IMG_W - 1));
    const int ix_lo = (int)sx_first;
    const int abase = ix_lo & ~3;           // 16B-aligned start of staged span

    // --- stage 6 row segments (coalesced float4) ---
    // r = c*2 + (0: row iy0, 1: row iy0+1). iy0 <= 2045 here, all in-bounds.
    #pragma unroll
    for (int i = tid; i < 6 * SEG_F4; i += SIZE) {
        const int r   = i / SEG_F4;
        const int j   = i - r * SEG_F4;
        const int c   = r >> 1;
        const int row = iy0 + (r & 1);
        const float4 v = __ldg((const float4*)(img + c * PLANE + (row << 11) + abase) + j);
        *((float4*)(tile + r * STRIDE) + j) = v;
    }
    __syncthreads();

    // --- per-pixel bilinear from smem ---
    float sx = fmaf((float)tid, g.z, g.x);
    sx = fminf(fmaxf(sx, 0.0f), (float)(IMG_W - 1));
    const int   ix0 = (int)sx;
    const float fx  = sx - (float)ix0;
    const int   k   = ix0 - abase;          // 0..325, k+1 < 328

    const float ex = 1.0f - fx;
    const float ey = 1.0f - fy;
    const float w00 = ex * ey;
    const float w01 = fx * ey;
    const float w10 = ex * fy;
    const float w11 = fx * fy;

    const float* t0 = tile + k;             // c=0 rows at 0,1
    const float a00 = t0[0 * STRIDE], a01 = t0[0 * STRIDE + 1];
    const float a10 = t0[1 * STRIDE], a11 = t0[1 * STRIDE + 1];
    const float b00 = t0[2 * STRIDE], b01 = t0[2 * STRIDE + 1];
    const float b10 = t0[3 * STRIDE], b11 = t0[3 * STRIDE + 1];
    const float c00 = t0[4 * STRIDE], c01 = t0[4 * STRIDE + 1];
    const float c10 = t0[5 * STRIDE], c11 = t0[5 * STRIDE + 1];

    const float sR = 1.0f / (255.0f * STD_R), bR = MEAN_R / STD_R;
    const float sG = 1.0f / (255.0f * STD_G), bG = MEAN_G / STD_G;
    const float sB = 1.0f / (255.0f * STD_B), bB = MEAN_B / STD_B;

    float vR = a00 * w00; vR = fmaf(a01, w01, vR); vR = fmaf(a10, w10, vR); vR = fmaf(a11, w11, vR);
    float vG = b00 * w00; vG = fmaf(b01, w01, vG); vG = fmaf(b10, w10, vG); vG = fmaf(b11, w11, vG);
    float vB = c00 * w00; vB = fmaf(c01, w01, vB); vB = fmaf(c10, w10, vB); vB = fmaf(c11, w11, vB);

    float* __restrict__ dst = out + ((long long)n * 3 * OUT_PLANE) + y * SIZE + tid;
    dst[0]             = fmaf(vR, sR, -bR);
    dst[OUT_PLANE]     = fmaf(vG, sG, -bG);
    dst[2 * OUT_PLANE] = fmaf(vB, sB, -bB);
}

extern "C" void kernel_launch(void* const* d_in, const int* in_sizes, int n_in,
                              void* d_out, int out_size)
{
    const float* img    = (const float*)d_in[0];
    const int*   bboxes = (const int*)d_in[3];
    float* out = (float*)d_out;

    const int N = in_sizes[3] / 4;

    geom_kernel<<<(N + 255) / 256, 256>>>(bboxes, N);

    dim3 grid(SIZE, N, 1);
    dim3 block(SIZE, 1, 1);
    patch_extract_kernel<<<grid, block>>>(img, out);
}

// round 6
// speedup vs baseline: 1.5096x; 1.5096x over previous
#include <cuda_runtime.h>

// PatchExtractor: crop(center square of bbox) + bilinear 224x224 + CLIP norm.
// R4: back to direct-gather (R2) + 2 output rows per thread for double MLP.
//
// img    : [3, 2048, 2048] fp32
// bboxes : [N, 4] int32 (xyxy)
// out    : [N, 3, 224, 224] fp32

#define SIZE 224
#define IMG_W 2048
#define IMG_H 2048
#define PLANE (IMG_H * IMG_W)
#define OUT_PLANE (SIZE * SIZE)
#define MAX_N 1024

#define MEAN_R 0.48145466f
#define MEAN_G 0.4578275f
#define MEAN_B 0.40821073f
#define STD_R  0.26862954f
#define STD_G  0.26130258f
#define STD_B  0.27577711f

// Per-patch geometry: {ax, ay, step, unused};  sx = ax + x*step
__device__ float4 g_geom[MAX_N];

__global__ void geom_kernel(const int* __restrict__ bboxes, int N)
{
    int n = blockIdx.x * blockDim.x + threadIdx.x;
    if (n >= N) return;
    const float x0 = (float)bboxes[4 * n + 0];
    const float y0 = (float)bboxes[4 * n + 1];
    const float x1 = (float)bboxes[4 * n + 2];
    const float y1 = (float)bboxes[4 * n + 3];
    const float side = fminf(x1 - x0, y1 - y0);
    const float step = side * (1.0f / (float)SIZE);
    const float ax = 0.5f * (x0 + x1) - 0.5f * side + 0.5f * step - 0.5f;
    const float ay = 0.5f * (y0 + y1) - 0.5f * side + 0.5f * step - 0.5f;
    g_geom[n] = make_float4(ax, ay, step, 0.0f);
}

__global__ __launch_bounds__(SIZE)
void patch_extract_kernel(const float* __restrict__ img,
                          float* __restrict__ out)
{
    const int y0 = blockIdx.x * 2;  // first of the two output rows
    const int n  = blockIdx.y;      // patch
    const int x  = threadIdx.x;     // output col

    const float4 g = g_geom[n];

    // ---- shared x-geometry (both rows) ----
    float sx = fmaf((float)x, g.z, g.x);
    sx = fminf(fmaxf(sx, 0.0f), (float)(IMG_W - 1));
    const int   ix0 = (int)sx;
    const float fx  = sx - (float)ix0;
    const float ex  = 1.0f - fx;

    // ---- per-row y-geometry ----
    float syA = fmaf((float)y0, g.z, g.y);
    float syB = syA + g.z;
    syA = fminf(fmaxf(syA, 0.0f), (float)(IMG_H - 1));
    syB = fminf(fmaxf(syB, 0.0f), (float)(IMG_H - 1));
    const int   iyA = (int)syA;
    const int   iyB = (int)syB;
    const float fyA = syA - (float)iyA;
    const float fyB = syB - (float)iyB;

    // bbox construction guarantees ix0+1 <= 2047, iy+1 <= 2047 (no clamps)
    const int oA0 = (iyA << 11) + ix0;   // row iyA
    const int oA1 = oA0 + IMG_W;         // row iyA+1
    const int oB0 = (iyB << 11) + ix0;   // row iyB
    const int oB1 = oB0 + IMG_W;         // row iyB+1

    const float* __restrict__ p0 = img;
    const float* __restrict__ p1 = img + PLANE;
    const float* __restrict__ p2 = img + 2 * PLANE;

    // ---- 24 gathers hoisted (MLP=24); many are L1 hits of each other ----
    const float rA00 = __ldg(p0 + oA0), rA01 = __ldg(p0 + oA0 + 1);
    const float rA10 = __ldg(p0 + oA1), rA11 = __ldg(p0 + oA1 + 1);
    const float rB00 = __ldg(p0 + oB0), rB01 = __ldg(p0 + oB0 + 1);
    const float rB10 = __ldg(p0 + oB1), rB11 = __ldg(p0 + oB1 + 1);

    const float gA00 = __ldg(p1 + oA0), gA01 = __ldg(p1 + oA0 + 1);
    const float gA10 = __ldg(p1 + oA1), gA11 = __ldg(p1 + oA1 + 1);
    const float gB00 = __ldg(p1 + oB0), gB01 = __ldg(p1 + oB0 + 1);
    const float gB10 = __ldg(p1 + oB1), gB11 = __ldg(p1 + oB1 + 1);

    const float bA00 = __ldg(p2 + oA0), bA01 = __ldg(p2 + oA0 + 1);
    const float bA10 = __ldg(p2 + oA1), bA11 = __ldg(p2 + oA1 + 1);
    const float bB00 = __ldg(p2 + oB0), bB01 = __ldg(p2 + oB0 + 1);
    const float bB10 = __ldg(p2 + oB1), bB11 = __ldg(p2 + oB1 + 1);

    // ---- 8 bilinear weights (shared across channels) ----
    const float eyA = 1.0f - fyA, eyB = 1.0f - fyB;
    const float wA00 = ex * eyA, wA01 = fx * eyA, wA10 = ex * fyA, wA11 = fx * fyA;
    const float wB00 = ex * eyB, wB01 = fx * eyB, wB10 = ex * fyB, wB11 = fx * fyB;

    const float sR = 1.0f / (255.0f * STD_R), cR = MEAN_R / STD_R;
    const float sG = 1.0f / (255.0f * STD_G), cG = MEAN_G / STD_G;
    const float sB = 1.0f / (255.0f * STD_B), cB = MEAN_B / STD_B;

    float vRA = rA00 * wA00; vRA = fmaf(rA01, wA01, vRA); vRA = fmaf(rA10, wA10, vRA); vRA = fmaf(rA11, wA11, vRA);
    float vGA = gA00 * wA00; vGA = fmaf(gA01, wA01, vGA); vGA = fmaf(gA10, wA10, vGA); vGA = fmaf(gA11, wA11, vGA);
    float vBA = bA00 * wA00; vBA = fmaf(bA01, wA01, vBA); vBA = fmaf(bA10, wA10, vBA); vBA = fmaf(bA11, wA11, vBA);

    float vRB = rB00 * wB00; vRB = fmaf(rB01, wB01, vRB); vRB = fmaf(rB10, wB10, vRB); vRB = fmaf(rB11, wB11, vRB);
    float vGB = gB00 * wB00; vGB = fmaf(gB01, wB01, vGB); vGB = fmaf(gB10, wB10, vGB); vGB = fmaf(gB11, wB11, vGB);
    float vBB = bB00 * wB00; vBB = fmaf(bB01, wB01, vBB); vBB = fmaf(bB10, wB10, vBB); vBB = fmaf(bB11, wB11, vBB);

    float* __restrict__ dst = out + ((long long)n * 3 * OUT_PLANE) + y0 * SIZE + x;
    dst[0]                     = fmaf(vRA, sR, -cR);
    dst[SIZE]                  = fmaf(vRB, sR, -cR);
    dst[OUT_PLANE]             = fmaf(vGA, sG, -cG);
    dst[OUT_PLANE + SIZE]      = fmaf(vGB, sG, -cG);
    dst[2 * OUT_PLANE]         = fmaf(vBA, sB, -cB);
    dst[2 * OUT_PLANE + SIZE]  = fmaf(vBB, sB, -cB);
}

extern "C" void kernel_launch(void* const* d_in, const int* in_sizes, int n_in,
                              void* d_out, int out_size)
{
    const float* img    = (const float*)d_in[0];
    const int*   bboxes = (const int*)d_in[3];
    float* out = (float*)d_out;

    const int N = in_sizes[3] / 4;

    geom_kernel<<<(N + 255) / 256, 256>>>(bboxes, N);

    dim3 grid(SIZE / 2, N, 1);
    dim3 block(SIZE, 1, 1);
    patch_extract_kernel<<<grid, block>>>(img, out);
}

// round 8
// speedup vs baseline: 1.6447x; 1.0895x over previous
#include <cuda_runtime.h>

// PatchExtractor: crop(center square of bbox) + bilinear 224x224 + CLIP norm.
// R6: 4 output rows per thread (MLP=48 gathers/warp, near the LDG queue cap).
//
// img    : [3, 2048, 2048] fp32
// bboxes : [N, 4] int32 (xyxy)
// out    : [N, 3, 224, 224] fp32

#define SIZE 224
#define ROWS_PER_THREAD 4
#define IMG_W 2048
#define IMG_H 2048
#define PLANE (IMG_H * IMG_W)
#define OUT_PLANE (SIZE * SIZE)
#define MAX_N 1024

#define MEAN_R 0.48145466f
#define MEAN_G 0.4578275f
#define MEAN_B 0.40821073f
#define STD_R  0.26862954f
#define STD_G  0.26130258f
#define STD_B  0.27577711f

// Per-patch geometry: {ax, ay, step, unused};  sx = ax + x*step
__device__ float4 g_geom[MAX_N];

__global__ void geom_kernel(const int* __restrict__ bboxes, int N)
{
    int n = blockIdx.x * blockDim.x + threadIdx.x;
    if (n >= N) return;
    const float x0 = (float)bboxes[4 * n + 0];
    const float y0 = (float)bboxes[4 * n + 1];
    const float x1 = (float)bboxes[4 * n + 2];
    const float y1 = (float)bboxes[4 * n + 3];
    const float side = fminf(x1 - x0, y1 - y0);
    const float step = side * (1.0f / (float)SIZE);
    const float ax = 0.5f * (x0 + x1) - 0.5f * side + 0.5f * step - 0.5f;
    const float ay = 0.5f * (y0 + y1) - 0.5f * side + 0.5f * step - 0.5f;
    g_geom[n] = make_float4(ax, ay, step, 0.0f);
}

__global__ __launch_bounds__(SIZE)
void patch_extract_kernel(const float* __restrict__ img,
                          float* __restrict__ out)
{
    const int y0 = blockIdx.x * ROWS_PER_THREAD;  // first output row
    const int n  = blockIdx.y;                    // patch
    const int x  = threadIdx.x;                   // output col

    const float4 g = g_geom[n];

    // ---- shared x-geometry (all 4 rows) ----
    float sx = fmaf((float)x, g.z, g.x);
    sx = fminf(fmaxf(sx, 0.0f), (float)(IMG_W - 1));
    const int   ix0 = (int)sx;
    const float fx  = sx - (float)ix0;
    const float ex  = 1.0f - fx;

    // ---- per-row y-geometry ----
    int   o0[ROWS_PER_THREAD];
    float fy[ROWS_PER_THREAD];
    #pragma unroll
    for (int k = 0; k < ROWS_PER_THREAD; ++k) {
        float sy = fmaf((float)(y0 + k), g.z, g.y);
        sy = fminf(fmaxf(sy, 0.0f), (float)(IMG_H - 1));
        const int iy = (int)sy;
        fy[k] = sy - (float)iy;
        o0[k] = (iy << 11) + ix0;     // row iy; iy+1 <= 2047 guaranteed
    }

    const float* __restrict__ p0 = img;
    const float* __restrict__ p1 = img + PLANE;
    const float* __restrict__ p2 = img + 2 * PLANE;

    // ---- hoist all 48 gathers (MLP ~ LDG queue cap) ----
    float pr[ROWS_PER_THREAD][4], pg[ROWS_PER_THREAD][4], pb[ROWS_PER_THREAD][4];
    #pragma unroll
    for (int k = 0; k < ROWS_PER_THREAD; ++k) {
        const int a = o0[k];
        const int b = a + IMG_W;
        pr[k][0] = __ldg(p0 + a); pr[k][1] = __ldg(p0 + a + 1);
        pr[k][2] = __ldg(p0 + b); pr[k][3] = __ldg(p0 + b + 1);
        pg[k][0] = __ldg(p1 + a); pg[k][1] = __ldg(p1 + a + 1);
        pg[k][2] = __ldg(p1 + b); pg[k][3] = __ldg(p1 + b + 1);
        pb[k][0] = __ldg(p2 + a); pb[k][1] = __ldg(p2 + a + 1);
        pb[k][2] = __ldg(p2 + b); pb[k][3] = __ldg(p2 + b + 1);
    }

    const float sR = 1.0f / (255.0f * STD_R), cR = MEAN_R / STD_R;
    const float sG = 1.0f / (255.0f * STD_G), cG = MEAN_G / STD_G;
    const float sB = 1.0f / (255.0f * STD_B), cB = MEAN_B / STD_B;

    float* __restrict__ dst = out + ((long long)n * 3 * OUT_PLANE) + y0 * SIZE + x;

    #pragma unroll
    for (int k = 0; k < ROWS_PER_THREAD; ++k) {
        const float eyk = 1.0f - fy[k];
        const float w00 = ex * eyk, w01 = fx * eyk;
        const float w10 = ex * fy[k], w11 = fx * fy[k];

        float vR = pr[k][0] * w00; vR = fmaf(pr[k][1], w01, vR);
        vR = fmaf(pr[k][2], w10, vR); vR = fmaf(pr[k][3], w11, vR);
        float vG = pg[k][0] * w00; vG = fmaf(pg[k][1], w01, vG);
        vG = fmaf(pg[k][2], w10, vG); vG = fmaf(pg[k][3], w11, vG);
        float vB = pb[k][0] * w00; vB = fmaf(pb[k][1], w01, vB);
        vB = fmaf(pb[k][2], w10, vB); vB = fmaf(pb[k][3], w11, vB);

        dst[k * SIZE]                 = fmaf(vR, sR, -cR);
        dst[k * SIZE + OUT_PLANE]     = fmaf(vG, sG, -cG);
        dst[k * SIZE + 2 * OUT_PLANE] = fmaf(vB, sB, -cB);
    }
}

extern "C" void kernel_launch(void* const* d_in, const int* in_sizes, int n_in,
                              void* d_out, int out_size)
{
    const float* img    = (const float*)d_in[0];
    const int*   bboxes = (const int*)d_in[3];
    float* out = (float*)d_out;

    const int N = in_sizes[3] / 4;

    geom_kernel<<<(N + 255) / 256, 256>>>(bboxes, N);

    dim3 grid(SIZE / ROWS_PER_THREAD, N, 1);
    dim3 block(SIZE, 1, 1);
    patch_extract_kernel<<<grid, block>>>(img, out);
}